// round 6
// baseline (speedup 1.0000x reference)
#include <cuda_runtime.h>
#include <cuda_fp16.h>

// GraphConvolution SpMM: out = relu(segment_sum(values[e] * kernel[cols[e]], rows[e]) + bias)
// N=50000, NNZ=1.6M, UNITS=64.
// Round 5: 3 kernels only. Spill handling folded into SpMM (free when no
// spills), bias+relu always fused. Vectorized scatter loads, float4 prep.

#define UNITS 64
#define N_CAP 65536
#define SLOTS 80
#define SPILL_CAP 4096

__device__ int    g_count[N_CAP];
__device__ int2   g_bucket[(long long)N_CAP * SLOTS];  // {col, val-bits}
__device__ __half g_khalf[(long long)N_CAP * UNITS];   // fp16 copy of kernel
__device__ int    g_spill_cnt;
__device__ int    g_spill_row[SPILL_CAP];
__device__ int2   g_spill_edge[SPILL_CAP];

// Zero counts AND convert kernel matrix fp32 -> fp16 (float4 -> 2x half2, 8B store).
__global__ void gc_prep_kernel(const float* __restrict__ kern, int n) {
    int i = blockIdx.x * blockDim.x + threadIdx.x;
    if (i == 0) g_spill_cnt = 0;
    if (i < n) g_count[i] = 0;
    int quads = n * (UNITS / 4);               // float4 elements
    if (i < quads) {
        float4 f = ((const float4*)kern)[i];
        half2 lo = __floats2half2_rn(f.x, f.y);
        half2 hi = __floats2half2_rn(f.z, f.w);
        uint2 packed;
        packed.x = *(unsigned int*)&lo;
        packed.y = *(unsigned int*)&hi;
        ((uint2*)g_khalf)[i] = packed;
    }
}

// Slot-allocating scatter: count + sort in one pass.
// 8 consecutive edges/thread via int4/float4 loads; scalar tail path.
__global__ void gc_scatter_kernel(const int* __restrict__ rows,
                                  const int* __restrict__ cols,
                                  const float* __restrict__ values,
                                  int nnz) {
    int base = (blockIdx.x * blockDim.x + threadIdx.x) * 8;
    if (base >= nnz) return;

    int r[8], c[8];
    float v[8];
    int cnt;

    if (base + 8 <= nnz) {
        cnt = 8;
        int4 r0 = ((const int4*)rows)[(base >> 2) + 0];
        int4 r1 = ((const int4*)rows)[(base >> 2) + 1];
        int4 c0 = ((const int4*)cols)[(base >> 2) + 0];
        int4 c1 = ((const int4*)cols)[(base >> 2) + 1];
        float4 v0 = ((const float4*)values)[(base >> 2) + 0];
        float4 v1 = ((const float4*)values)[(base >> 2) + 1];
        r[0]=r0.x; r[1]=r0.y; r[2]=r0.z; r[3]=r0.w;
        r[4]=r1.x; r[5]=r1.y; r[6]=r1.z; r[7]=r1.w;
        c[0]=c0.x; c[1]=c0.y; c[2]=c0.z; c[3]=c0.w;
        c[4]=c1.x; c[5]=c1.y; c[6]=c1.z; c[7]=c1.w;
        v[0]=v0.x; v[1]=v0.y; v[2]=v0.z; v[3]=v0.w;
        v[4]=v1.x; v[5]=v1.y; v[6]=v1.z; v[7]=v1.w;
    } else {
        cnt = nnz - base;
        for (int j = 0; j < cnt; j++) {
            r[j] = rows[base + j];
            c[j] = cols[base + j];
            v[j] = values[base + j];
        }
    }

    int p[8];
    #pragma unroll
    for (int j = 0; j < 8; j++) {
        if (j < cnt) p[j] = atomicAdd(&g_count[r[j]], 1);
    }
    #pragma unroll
    for (int j = 0; j < 8; j++) {
        if (j < cnt) {
            if (p[j] < SLOTS) {
                g_bucket[(long long)r[j] * SLOTS + p[j]] =
                    make_int2(c[j], __float_as_int(v[j]));
            } else {
                int s = atomicAdd(&g_spill_cnt, 1);
                if (s < SPILL_CAP) {
                    g_spill_row[s]  = r[j];
                    g_spill_edge[s] = make_int2(c[j], __float_as_int(v[j]));
                }
            }
        }
    }
}

// One warp per row; lane l accumulates units {2l, 2l+1} in fp32, gathering
// half2 (4B/lane = 128B/warp per edge). Spill edges handled inline (broadcast
// scan of the tiny spill list — free when empty). Bias+relu always fused.
__global__ void gc_spmm_kernel(const float* __restrict__ bias,
                               float* __restrict__ out,
                               int n) {
    int warp = (blockIdx.x * blockDim.x + threadIdx.x) >> 5;
    int lane = threadIdx.x & 31;
    if (warp >= n) return;

    int cnt = g_count[warp];
    if (cnt > SLOTS) cnt = SLOTS;

    const int2* bk = g_bucket + (long long)warp * SLOTS;
    const int4* bp = (const int4*)bk;            // 2 edges per int4
    const half2* kh = (const half2*)g_khalf;     // [row*32 + lane]

    float ax = 0.0f, ay = 0.0f;
    int e = 0;
    #pragma unroll 1
    for (; e + 8 <= cnt; e += 8) {
        int4 q0 = bp[(e >> 1) + 0];
        int4 q1 = bp[(e >> 1) + 1];
        int4 q2 = bp[(e >> 1) + 2];
        int4 q3 = bp[(e >> 1) + 3];
        half2 h0 = kh[(long long)q0.x * 32 + lane];
        half2 h1 = kh[(long long)q0.z * 32 + lane];
        half2 h2 = kh[(long long)q1.x * 32 + lane];
        half2 h3 = kh[(long long)q1.z * 32 + lane];
        half2 h4 = kh[(long long)q2.x * 32 + lane];
        half2 h5 = kh[(long long)q2.z * 32 + lane];
        half2 h6 = kh[(long long)q3.x * 32 + lane];
        half2 h7 = kh[(long long)q3.z * 32 + lane];
        float2 k0 = __half22float2(h0);
        float2 k1 = __half22float2(h1);
        float2 k2 = __half22float2(h2);
        float2 k3 = __half22float2(h3);
        float2 k4 = __half22float2(h4);
        float2 k5 = __half22float2(h5);
        float2 k6 = __half22float2(h6);
        float2 k7 = __half22float2(h7);
        float v0 = __int_as_float(q0.y), v1 = __int_as_float(q0.w);
        float v2 = __int_as_float(q1.y), v3 = __int_as_float(q1.w);
        float v4 = __int_as_float(q2.y), v5 = __int_as_float(q2.w);
        float v6 = __int_as_float(q3.y), v7 = __int_as_float(q3.w);
        ax += v0 * k0.x;  ay += v0 * k0.y;
        ax += v1 * k1.x;  ay += v1 * k1.y;
        ax += v2 * k2.x;  ay += v2 * k2.y;
        ax += v3 * k3.x;  ay += v3 * k3.y;
        ax += v4 * k4.x;  ay += v4 * k4.y;
        ax += v5 * k5.x;  ay += v5 * k5.y;
        ax += v6 * k6.x;  ay += v6 * k6.y;
        ax += v7 * k7.x;  ay += v7 * k7.y;
    }
    for (; e < cnt; e++) {
        int2 ed = bk[e];
        float v = __int_as_float(ed.y);
        float2 k = __half22float2(kh[(long long)ed.x * 32 + lane]);
        ax += v * k.x;
        ay += v * k.y;
    }

    // Spill edges for this row (broadcast reads; spills==0 in practice).
    int spills = g_spill_cnt;
    if (spills > 0) {
        if (spills > SPILL_CAP) spills = SPILL_CAP;
        for (int s = 0; s < spills; s++) {
            if (g_spill_row[s] == warp) {
                int2 ed = g_spill_edge[s];
                float v = __int_as_float(ed.y);
                float2 k = __half22float2(kh[(long long)ed.x * 32 + lane]);
                ax += v * k.x;
                ay += v * k.y;
            }
        }
    }

    float2 b = ((const float2*)bias)[lane];
    float2 o;
    o.x = fmaxf(ax + b.x, 0.0f);
    o.y = fmaxf(ay + b.y, 0.0f);
    ((float2*)out)[(long long)warp * 32 + lane] = o;
}

extern "C" void kernel_launch(void* const* d_in, const int* in_sizes, int n_in,
                              void* d_out, int out_size) {
    const int*   rows   = (const int*)d_in[0];
    const int*   cols   = (const int*)d_in[1];
    const float* values = (const float*)d_in[2];
    const float* kern   = (const float*)d_in[3];
    const float* bias   = (const float*)d_in[4];
    float* out = (float*)d_out;

    int nnz = in_sizes[0];
    int n   = out_size / UNITS;

    const int T = 256;

    int prep_threads = n * (UNITS / 4);          // float4 granularity; covers counts
    gc_prep_kernel<<<(prep_threads + T - 1) / T, T>>>(kern, n);

    int sthreads = (nnz + 7) / 8;
    gc_scatter_kernel<<<(sthreads + T - 1) / T, T>>>(rows, cols, values, nnz);

    int blocks = (n * 32 + T - 1) / T;
    gc_spmm_kernel<<<blocks, T>>>(bias, out, n);
}

// round 7
// speedup vs baseline: 1.0599x; 1.0599x over previous
#include <cuda_runtime.h>
#include <cuda_fp16.h>

// GraphConvolution SpMM: out = relu(segment_sum(values[e] * kernel[cols[e]], rows[e]) + bias)
// N=50000, NNZ=1.6M, UNITS=64.
// Round 6: R4's strided scatter (measured good) + R5's 3-launch structure
// (spill folded into SpMM, fused bias+relu) + float4 prep.

#define UNITS 64
#define N_CAP 65536
#define SLOTS 80
#define SPILL_CAP 4096

__device__ int    g_count[N_CAP];
__device__ int2   g_bucket[(long long)N_CAP * SLOTS];  // {col, val-bits}
__device__ __half g_khalf[(long long)N_CAP * UNITS];   // fp16 copy of kernel
__device__ int    g_spill_cnt;
__device__ int    g_spill_row[SPILL_CAP];
__device__ int2   g_spill_edge[SPILL_CAP];

// Zero counts AND convert kernel matrix fp32 -> fp16 (float4 -> 2x half2, 8B store).
__global__ void gc_prep_kernel(const float* __restrict__ kern, int n) {
    int i = blockIdx.x * blockDim.x + threadIdx.x;
    if (i == 0) g_spill_cnt = 0;
    if (i < n) g_count[i] = 0;
    int quads = n * (UNITS / 4);               // float4 elements
    if (i < quads) {
        float4 f = ((const float4*)kern)[i];
        half2 lo = __floats2half2_rn(f.x, f.y);
        half2 hi = __floats2half2_rn(f.z, f.w);
        uint2 packed;
        packed.x = *(unsigned int*)&lo;
        packed.y = *(unsigned int*)&hi;
        ((uint2*)g_khalf)[i] = packed;
    }
}

// Slot-allocating scatter: count + sort in one pass.
// 8 edges per thread, warp-coalesced strides, explicit MLP (R4 form).
__global__ void gc_scatter_kernel(const int* __restrict__ rows,
                                  const int* __restrict__ cols,
                                  const float* __restrict__ values,
                                  int nnz, int stride) {
    int tid = blockIdx.x * blockDim.x + threadIdx.x;

    int r[8], c[8];
    float v[8];
    bool ok[8];
    #pragma unroll
    for (int j = 0; j < 8; j++) {
        int e = tid + j * stride;
        ok[j] = (e < nnz);
        if (ok[j]) {
            r[j] = rows[e];
            c[j] = cols[e];
            v[j] = values[e];
        }
    }
    int p[8];
    #pragma unroll
    for (int j = 0; j < 8; j++) {
        if (ok[j]) p[j] = atomicAdd(&g_count[r[j]], 1);
    }
    #pragma unroll
    for (int j = 0; j < 8; j++) {
        if (ok[j]) {
            if (p[j] < SLOTS) {
                g_bucket[(long long)r[j] * SLOTS + p[j]] =
                    make_int2(c[j], __float_as_int(v[j]));
            } else {
                int s = atomicAdd(&g_spill_cnt, 1);
                if (s < SPILL_CAP) {
                    g_spill_row[s]  = r[j];
                    g_spill_edge[s] = make_int2(c[j], __float_as_int(v[j]));
                }
            }
        }
    }
}

// One warp per row; lane l accumulates units {2l, 2l+1} in fp32, gathering
// half2 (4B/lane = 128B/warp per edge). Spill edges handled inline (broadcast
// scan of the tiny spill list — free when empty). Bias+relu always fused.
__global__ void gc_spmm_kernel(const float* __restrict__ bias,
                               float* __restrict__ out,
                               int n) {
    int warp = (blockIdx.x * blockDim.x + threadIdx.x) >> 5;
    int lane = threadIdx.x & 31;
    if (warp >= n) return;

    int cnt = g_count[warp];
    if (cnt > SLOTS) cnt = SLOTS;

    const int2* bk = g_bucket + (long long)warp * SLOTS;
    const int4* bp = (const int4*)bk;            // 2 edges per int4
    const half2* kh = (const half2*)g_khalf;     // [row*32 + lane]

    float ax = 0.0f, ay = 0.0f;
    int e = 0;
    #pragma unroll 1
    for (; e + 8 <= cnt; e += 8) {
        int4 q0 = bp[(e >> 1) + 0];
        int4 q1 = bp[(e >> 1) + 1];
        int4 q2 = bp[(e >> 1) + 2];
        int4 q3 = bp[(e >> 1) + 3];
        half2 h0 = kh[(long long)q0.x * 32 + lane];
        half2 h1 = kh[(long long)q0.z * 32 + lane];
        half2 h2 = kh[(long long)q1.x * 32 + lane];
        half2 h3 = kh[(long long)q1.z * 32 + lane];
        half2 h4 = kh[(long long)q2.x * 32 + lane];
        half2 h5 = kh[(long long)q2.z * 32 + lane];
        half2 h6 = kh[(long long)q3.x * 32 + lane];
        half2 h7 = kh[(long long)q3.z * 32 + lane];
        float2 k0 = __half22float2(h0);
        float2 k1 = __half22float2(h1);
        float2 k2 = __half22float2(h2);
        float2 k3 = __half22float2(h3);
        float2 k4 = __half22float2(h4);
        float2 k5 = __half22float2(h5);
        float2 k6 = __half22float2(h6);
        float2 k7 = __half22float2(h7);
        float v0 = __int_as_float(q0.y), v1 = __int_as_float(q0.w);
        float v2 = __int_as_float(q1.y), v3 = __int_as_float(q1.w);
        float v4 = __int_as_float(q2.y), v5 = __int_as_float(q2.w);
        float v6 = __int_as_float(q3.y), v7 = __int_as_float(q3.w);
        ax += v0 * k0.x;  ay += v0 * k0.y;
        ax += v1 * k1.x;  ay += v1 * k1.y;
        ax += v2 * k2.x;  ay += v2 * k2.y;
        ax += v3 * k3.x;  ay += v3 * k3.y;
        ax += v4 * k4.x;  ay += v4 * k4.y;
        ax += v5 * k5.x;  ay += v5 * k5.y;
        ax += v6 * k6.x;  ay += v6 * k6.y;
        ax += v7 * k7.x;  ay += v7 * k7.y;
    }
    for (; e < cnt; e++) {
        int2 ed = bk[e];
        float v = __int_as_float(ed.y);
        float2 k = __half22float2(kh[(long long)ed.x * 32 + lane]);
        ax += v * k.x;
        ay += v * k.y;
    }

    // Spill edges for this row (broadcast reads; spills==0 in practice).
    int spills = g_spill_cnt;
    if (spills > 0) {
        if (spills > SPILL_CAP) spills = SPILL_CAP;
        for (int s = 0; s < spills; s++) {
            if (g_spill_row[s] == warp) {
                int2 ed = g_spill_edge[s];
                float v = __int_as_float(ed.y);
                float2 k = __half22float2(kh[(long long)ed.x * 32 + lane]);
                ax += v * k.x;
                ay += v * k.y;
            }
        }
    }

    float2 b = ((const float2*)bias)[lane];
    float2 o;
    o.x = fmaxf(ax + b.x, 0.0f);
    o.y = fmaxf(ay + b.y, 0.0f);
    ((float2*)out)[(long long)warp * 32 + lane] = o;
}

extern "C" void kernel_launch(void* const* d_in, const int* in_sizes, int n_in,
                              void* d_out, int out_size) {
    const int*   rows   = (const int*)d_in[0];
    const int*   cols   = (const int*)d_in[1];
    const float* values = (const float*)d_in[2];
    const float* bias   = (const float*)d_in[4];
    const float* kern   = (const float*)d_in[3];
    float* out = (float*)d_out;

    int nnz = in_sizes[0];
    int n   = out_size / UNITS;

    const int T = 256;

    int prep_threads = n * (UNITS / 4);          // float4 granularity; covers counts
    gc_prep_kernel<<<(prep_threads + T - 1) / T, T>>>(kern, n);

    int sthreads = (nnz + 7) / 8;
    int sblocks  = (sthreads + T - 1) / T;
    gc_scatter_kernel<<<sblocks, T>>>(rows, cols, values, nnz, sblocks * T);

    int blocks = (n * 32 + T - 1) / T;
    gc_spmm_kernel<<<blocks, T>>>(bias, out, n);
}

// round 8
// speedup vs baseline: 1.1039x; 1.0414x over previous
#include <cuda_runtime.h>
#include <cuda_fp16.h>

// GraphConvolution SpMM: out = relu(segment_sum(values[e] * kernel[cols[e]], rows[e]) + bias)
// N=50000, NNZ=1.6M, UNITS=64.
// Round 7: khalf fp32->fp16 conversion folded into the latency-bound scatter
// kernel (hides its bandwidth under atomic latency); prep reduced to count
// zeroing; SpMM main loop unrolled 16 with unroll-4 mid-tail.

#define UNITS 64
#define N_CAP 65536
#define SLOTS 80
#define SPILL_CAP 4096

__device__ int    g_count[N_CAP];
__device__ int2   g_bucket[(long long)N_CAP * SLOTS];  // {col, val-bits}
__device__ __half g_khalf[(long long)N_CAP * UNITS];   // fp16 copy of kernel
__device__ int    g_spill_cnt;
__device__ int    g_spill_row[SPILL_CAP];
__device__ int2   g_spill_edge[SPILL_CAP];

// Zero counts + spill counter only (tiny).
__global__ void gc_zero_kernel(int n) {
    int i = blockIdx.x * blockDim.x + threadIdx.x;
    if (i == 0) g_spill_cnt = 0;
    if (i < n) g_count[i] = 0;
}

// Slot-allocating scatter (R4 strided 8-edges/thread form) + interleaved
// fp32->fp16 kernel-matrix conversion (grid-stride float4 loop). The
// conversion's streaming loads/stores fill the latency shadow of the
// edge-load -> atomic -> random-store chains.
__global__ void gc_scatter_kernel(const int* __restrict__ rows,
                                  const int* __restrict__ cols,
                                  const float* __restrict__ values,
                                  const float* __restrict__ kern,
                                  int nnz, int stride, int quads) {
    int tid = blockIdx.x * blockDim.x + threadIdx.x;

    // Edge front-end: strided, 8 per thread.
    int r[8], c[8];
    float v[8];
    bool ok[8];
    #pragma unroll
    for (int j = 0; j < 8; j++) {
        int e = tid + j * stride;
        ok[j] = (e < nnz);
        if (ok[j]) {
            r[j] = rows[e];
            c[j] = cols[e];
            v[j] = values[e];
        }
    }

    // Conversion work: independent of the edge chain; overlaps atomics below.
    int nthreads = stride;   // stride == gridDim.x * blockDim.x
    for (int q = tid; q < quads; q += nthreads) {
        float4 f = ((const float4*)kern)[q];
        half2 lo = __floats2half2_rn(f.x, f.y);
        half2 hi = __floats2half2_rn(f.z, f.w);
        uint2 packed;
        packed.x = *(unsigned int*)&lo;
        packed.y = *(unsigned int*)&hi;
        ((uint2*)g_khalf)[q] = packed;
    }

    int p[8];
    #pragma unroll
    for (int j = 0; j < 8; j++) {
        if (ok[j]) p[j] = atomicAdd(&g_count[r[j]], 1);
    }
    #pragma unroll
    for (int j = 0; j < 8; j++) {
        if (ok[j]) {
            if (p[j] < SLOTS) {
                g_bucket[(long long)r[j] * SLOTS + p[j]] =
                    make_int2(c[j], __float_as_int(v[j]));
            } else {
                int s = atomicAdd(&g_spill_cnt, 1);
                if (s < SPILL_CAP) {
                    g_spill_row[s]  = r[j];
                    g_spill_edge[s] = make_int2(c[j], __float_as_int(v[j]));
                }
            }
        }
    }
}

// One warp per row; lane l accumulates units {2l, 2l+1} in fp32, gathering
// half2 (4B/lane = 128B/warp per edge). Unroll 16 main loop, unroll 4 mid,
// scalar tail. Spill edges handled inline; bias+relu fused.
__global__ void gc_spmm_kernel(const float* __restrict__ bias,
                               float* __restrict__ out,
                               int n) {
    int warp = (blockIdx.x * blockDim.x + threadIdx.x) >> 5;
    int lane = threadIdx.x & 31;
    if (warp >= n) return;

    int cnt = g_count[warp];
    if (cnt > SLOTS) cnt = SLOTS;

    const int2* bk = g_bucket + (long long)warp * SLOTS;
    const int4* bp = (const int4*)bk;            // 2 edges per int4
    const half2* kh = (const half2*)g_khalf;     // [row*32 + lane]

    float ax = 0.0f, ay = 0.0f;
    int e = 0;

    #pragma unroll 1
    for (; e + 16 <= cnt; e += 16) {
        int4 q[8];
        #pragma unroll
        for (int j = 0; j < 8; j++) q[j] = bp[(e >> 1) + j];
        half2 h[16];
        #pragma unroll
        for (int j = 0; j < 8; j++) {
            h[2 * j]     = kh[(long long)q[j].x * 32 + lane];
            h[2 * j + 1] = kh[(long long)q[j].z * 32 + lane];
        }
        #pragma unroll
        for (int j = 0; j < 8; j++) {
            float2 ka = __half22float2(h[2 * j]);
            float2 kb = __half22float2(h[2 * j + 1]);
            float va = __int_as_float(q[j].y);
            float vb = __int_as_float(q[j].w);
            ax += va * ka.x;  ay += va * ka.y;
            ax += vb * kb.x;  ay += vb * kb.y;
        }
    }
    #pragma unroll 1
    for (; e + 4 <= cnt; e += 4) {
        int4 q0 = bp[(e >> 1) + 0];
        int4 q1 = bp[(e >> 1) + 1];
        half2 h0 = kh[(long long)q0.x * 32 + lane];
        half2 h1 = kh[(long long)q0.z * 32 + lane];
        half2 h2 = kh[(long long)q1.x * 32 + lane];
        half2 h3 = kh[(long long)q1.z * 32 + lane];
        float2 k0 = __half22float2(h0);
        float2 k1 = __half22float2(h1);
        float2 k2 = __half22float2(h2);
        float2 k3 = __half22float2(h3);
        float v0 = __int_as_float(q0.y), v1 = __int_as_float(q0.w);
        float v2 = __int_as_float(q1.y), v3 = __int_as_float(q1.w);
        ax += v0 * k0.x;  ay += v0 * k0.y;
        ax += v1 * k1.x;  ay += v1 * k1.y;
        ax += v2 * k2.x;  ay += v2 * k2.y;
        ax += v3 * k3.x;  ay += v3 * k3.y;
    }
    for (; e < cnt; e++) {
        int2 ed = bk[e];
        float v = __int_as_float(ed.y);
        float2 k = __half22float2(kh[(long long)ed.x * 32 + lane]);
        ax += v * k.x;
        ay += v * k.y;
    }

    // Spill edges for this row (broadcast reads; spills==0 in practice).
    int spills = g_spill_cnt;
    if (spills > 0) {
        if (spills > SPILL_CAP) spills = SPILL_CAP;
        for (int s = 0; s < spills; s++) {
            if (g_spill_row[s] == warp) {
                int2 ed = g_spill_edge[s];
                float v = __int_as_float(ed.y);
                float2 k = __half22float2(kh[(long long)ed.x * 32 + lane]);
                ax += v * k.x;
                ay += v * k.y;
            }
        }
    }

    float2 b = ((const float2*)bias)[lane];
    float2 o;
    o.x = fmaxf(ax + b.x, 0.0f);
    o.y = fmaxf(ay + b.y, 0.0f);
    ((float2*)out)[(long long)warp * 32 + lane] = o;
}

extern "C" void kernel_launch(void* const* d_in, const int* in_sizes, int n_in,
                              void* d_out, int out_size) {
    const int*   rows   = (const int*)d_in[0];
    const int*   cols   = (const int*)d_in[1];
    const float* values = (const float*)d_in[2];
    const float* kern   = (const float*)d_in[3];
    const float* bias   = (const float*)d_in[4];
    float* out = (float*)d_out;

    int nnz = in_sizes[0];
    int n   = out_size / UNITS;

    const int T = 256;

    gc_zero_kernel<<<(n + T - 1) / T, T>>>(n);

    int sthreads = (nnz + 7) / 8;
    int sblocks  = (sthreads + T - 1) / T;
    int quads    = n * (UNITS / 4);              // float4 elements of kernel matrix
    gc_scatter_kernel<<<sblocks, T>>>(rows, cols, values, kern,
                                      nnz, sblocks * T, quads);

    int blocks = (n * 32 + T - 1) / T;
    gc_spmm_kernel<<<blocks, T>>>(bias, out, n);
}